// round 2
// baseline (speedup 1.0000x reference)
#include <cuda_runtime.h>

// Conv2d: x(32,128,112,112) fp32, w(256,128,3,3), stride 2, VALID -> out(32,256,55,55)
// Implicit GEMM: M = 32*55*55 = 96800 (b,oh,ow), N = 256 (cout), K = 128*9 = 1152 (cin,kh,kw)

#define B_   32
#define CIN  128
#define HIN  112
#define WIN  112
#define COUT 256
#define OHW  55
#define KTOT 1152
#define M_TOT (B_ * OHW * OHW)   // 96800

#define BM 128
#define BN 128
#define BK 8
#define TM 8
#define TN 8

__global__ __launch_bounds__(256, 2)
void conv_igemm_kernel(const float* __restrict__ x,
                       const float* __restrict__ w,
                       float* __restrict__ out) {
    __shared__ float As[BK][BM];
    __shared__ float Bs[BK][BN];

    const int tid = threadIdx.x;
    const int m0 = blockIdx.x * BM;
    const int n0 = blockIdx.y * BN;

    // ---- A (im2col of x) load mapping -------------------------------------
    // 1024 tile elems, 4 per thread: m = tid&127 (fixed), k-rows {kr0, kr0+2, kr0+4, kr0+6}
    const int a_mloc = tid & 127;
    const int a_kr0  = tid >> 7;        // 0 or 1
    const int a_m    = m0 + a_mloc;
    const bool a_ok  = (a_m < M_TOT);

    int aoh2 = 0, aow2 = 0;
    const float* xb = x;
    if (a_ok) {
        int b   = a_m / (OHW * OHW);
        int rem = a_m - b * (OHW * OHW);
        int oh  = rem / OHW;
        int ow  = rem - oh * OHW;
        aoh2 = 2 * oh;
        aow2 = 2 * ow;
        xb = x + (long)b * (CIN * HIN * WIN);
    }

    // ---- B (weights) load mapping -----------------------------------------
    // 128 n-cols x 8 k: each thread loads one float4. W is [COUT][1152], K contiguous.
    const int b_n    = tid >> 1;          // 0..127
    const int b_half = (tid & 1) * 4;     // 0 or 4
    const float* wptr = w + (long)(n0 + b_n) * KTOT + b_half;

    // ---- compute mapping ---------------------------------------------------
    const int ty = tid >> 4;   // 0..15 -> 8 m-rows each
    const int tx = tid & 15;   // 0..15 -> 8 n-cols each

    float acc[TM][TN];
    #pragma unroll
    for (int i = 0; i < TM; i++)
        #pragma unroll
        for (int j = 0; j < TN; j++)
            acc[i][j] = 0.0f;

    for (int k0 = 0; k0 < KTOT; k0 += BK) {
        // Load A tile (gather with on-the-fly im2col index)
        #pragma unroll
        for (int j = 0; j < 4; j++) {
            const int kr = a_kr0 + j * 2;
            float v = 0.0f;
            if (a_ok) {
                const int k   = k0 + kr;
                const int cin = k / 9;
                const int r   = k - cin * 9;
                const int kh  = r / 3;
                const int kw  = r - kh * 3;
                v = xb[(cin * HIN + (aoh2 + kh)) * WIN + (aow2 + kw)];
            }
            As[kr][a_mloc] = v;
        }
        // Load B tile (vectorized; fully L2-resident, weights are 1.2 MB)
        const float4 bv = *(const float4*)(wptr + k0);
        Bs[b_half + 0][b_n] = bv.x;
        Bs[b_half + 1][b_n] = bv.y;
        Bs[b_half + 2][b_n] = bv.z;
        Bs[b_half + 3][b_n] = bv.w;

        __syncthreads();

        #pragma unroll
        for (int kk = 0; kk < BK; kk++) {
            float a[TM], bb[TN];
            #pragma unroll
            for (int i = 0; i < TM; i++) a[i]  = As[kk][ty * TM + i];
            #pragma unroll
            for (int j = 0; j < TN; j++) bb[j] = Bs[kk][tx * TN + j];
            #pragma unroll
            for (int i = 0; i < TM; i++)
                #pragma unroll
                for (int j = 0; j < TN; j++)
                    acc[i][j] = fmaf(a[i], bb[j], acc[i][j]);
        }

        __syncthreads();
    }

    // ---- epilogue: scatter to NCHW output ----------------------------------
    #pragma unroll
    for (int i = 0; i < TM; i++) {
        const int m = m0 + ty * TM + i;
        if (m >= M_TOT) continue;
        int b   = m / (OHW * OHW);
        int rem = m - b * (OHW * OHW);
        int oh  = rem / OHW;
        int ow  = rem - oh * OHW;
        float* op = out + (((long)b * COUT + n0 + tx * TN) * OHW + oh) * OHW + ow;
        #pragma unroll
        for (int j = 0; j < TN; j++)
            op[(long)j * OHW * OHW] = acc[i][j];
    }
}

extern "C" void kernel_launch(void* const* d_in, const int* in_sizes, int n_in,
                              void* d_out, int out_size) {
    const float* x = (const float*)d_in[0];
    const float* w = (const float*)d_in[1];
    float* out = (float*)d_out;

    dim3 grid((M_TOT + BM - 1) / BM, COUT / BN);  // (757, 2)
    dim3 block(256);
    conv_igemm_kernel<<<grid, block>>>(x, w, out);
}

// round 6
// speedup vs baseline: 1.4524x; 1.4524x over previous
#include <cuda_runtime.h>
#include <cstdint>

// Conv2d: x(32,128,112,112) fp32, w(256,128,3,3), stride 2, VALID -> out(32,256,55,55)
// Implicit GEMM on mma.sync m16n8k8 tf32 (arch-neutral PTX; tcgen05 is rejected by
// this harness's ptxas target sm_103 without the 'a' suffix).
//   M = 32*55*55 = 96800, N = 256, K = 1152

#define B_    32
#define CIN   128
#define HIN   112
#define WIN   112
#define COUT  256
#define OHW   55
#define OHW2  (OHW*OHW)          // 3025
#define KTOT  1152
#define M_TOT (B_*OHW2)          // 96800
#define CHW   (CIN*HIN*WIN)

#define BM 128
#define BN 128
#define BK 32
#define NCHUNK (KTOT/BK)         // 36
#define SLD 36                   // smem row stride in floats (pad 4)

// smem layout in floats
#define OFF_A0 0
#define OFF_B0 (128*SLD)         // 4608
#define OFF_A1 (2*128*SLD)       // 9216
#define OFF_B1 (3*128*SLD)       // 13824
#define OFF_TAB (4*128*SLD)      // 18432 floats -> int table region
#define SMEM_BYTES (OFF_TAB*4 + KTOT*4)   // 78336 B

__device__ __forceinline__ uint32_t f2tf32(float f) {
    uint32_t r;
    asm("cvt.rna.tf32.f32 %0, %1;" : "=r"(r) : "f"(f));
    return r;
}

__device__ __forceinline__ void mma_tf32(float d[4],
                                         uint32_t a0, uint32_t a1, uint32_t a2, uint32_t a3,
                                         uint32_t b0, uint32_t b1) {
    asm volatile(
        "mma.sync.aligned.m16n8k8.row.col.f32.tf32.tf32.f32 "
        "{%0,%1,%2,%3}, {%4,%5,%6,%7}, {%8,%9}, {%0,%1,%2,%3};"
        : "+f"(d[0]), "+f"(d[1]), "+f"(d[2]), "+f"(d[3])
        : "r"(a0), "r"(a1), "r"(a2), "r"(a3), "r"(b0), "r"(b1));
}

__global__ void __launch_bounds__(256)
conv_mma_kernel(const float* __restrict__ x,
                const float* __restrict__ w,
                float* __restrict__ out) {
    extern __shared__ float smem[];
    int* offtab = (int*)(smem + OFF_TAB);

    const int tid  = threadIdx.x;
    const int wid  = tid >> 5;
    const int lane = tid & 31;
    const int m0 = blockIdx.x * BM;
    const int n0 = blockIdx.y * BN;

    // ---- producer mapping: 256 threads, each owns (row rsel+32j, k cols kk*4..+3) ----
    const int kk   = tid & 7;     // 4-k group within 32-k chunk
    const int rsel = tid >> 3;    // 0..31

    // im2col offset table: off[k] = cin*HW + kh*W + kw
    for (int k = tid; k < KTOT; k += 256) {
        int cin = k / 9, r = k - cin * 9;
        int kh = r / 3, kw = r - kh * 3;
        offtab[k] = cin * (HIN * WIN) + kh * WIN + kw;
    }

    // A row bases (x pixel origin per output position)
    int  abase[4];
    bool avalid[4];
    #pragma unroll
    for (int j = 0; j < 4; j++) {
        int m = m0 + j * 32 + rsel;
        avalid[j] = (m < M_TOT);
        int mm  = avalid[j] ? m : 0;
        int b   = mm / OHW2;
        int rem = mm - b * OHW2;
        int oh  = rem / OHW;
        int ow  = rem - oh * OHW;
        abase[j] = b * CHW + (2 * oh) * WIN + 2 * ow;
    }
    const float* wbase = w + (long)(n0 + rsel) * KTOT + kk * 4;

    __syncthreads();   // offtab ready

    // permuted column base: k = k0 + kk*4 + e  ->  col' = (kk>>1)*8 + e*2 + (kk&1)
    const int colp = (kk >> 1) * 8 + (kk & 1);

    // ---- compute mapping: 8 warps = 2(M) x 4(N), warp tile 64x32 ----
    const int wm = wid & 1;
    const int wn = wid >> 1;
    const int lr = lane >> 2;      // 0..7
    const int lc = lane & 3;       // 0..3

    float d[4][4][4];              // [tm][tn][frag]
    #pragma unroll
    for (int a = 0; a < 4; a++)
        #pragma unroll
        for (int b = 0; b < 4; b++)
            #pragma unroll
            for (int c = 0; c < 4; c++) d[a][b][c] = 0.0f;

    float areg[4][4], breg[4][4];

    // ---- chunk 0: load + store ----
    {
        const int k0 = 0;
        int ko[4];
        #pragma unroll
        for (int e = 0; e < 4; e++) ko[e] = offtab[k0 + kk * 4 + e];
        #pragma unroll
        for (int j = 0; j < 4; j++) {
            #pragma unroll
            for (int e = 0; e < 4; e++)
                areg[j][e] = avalid[j] ? __ldg(x + abase[j] + ko[e]) : 0.0f;
            const float4 bv = *(const float4*)(wbase + (long)j * 32 * KTOT + k0);
            breg[j][0] = bv.x; breg[j][1] = bv.y; breg[j][2] = bv.z; breg[j][3] = bv.w;
        }
        float* A = smem + OFF_A0;
        float* Bs = smem + OFF_B0;
        #pragma unroll
        for (int j = 0; j < 4; j++) {
            int row = j * 32 + rsel;
            #pragma unroll
            for (int e = 0; e < 4; e++) {
                A [row * SLD + colp + e * 2] = __uint_as_float(f2tf32(areg[j][e]));
                Bs[row * SLD + colp + e * 2] = __uint_as_float(f2tf32(breg[j][e]));
            }
        }
    }
    __syncthreads();

    for (int i = 0; i < NCHUNK; i++) {
        // ---- prefetch chunk i+1 into regs ----
        if (i + 1 < NCHUNK) {
            const int k0 = (i + 1) * BK;
            int ko[4];
            #pragma unroll
            for (int e = 0; e < 4; e++) ko[e] = offtab[k0 + kk * 4 + e];
            #pragma unroll
            for (int j = 0; j < 4; j++) {
                #pragma unroll
                for (int e = 0; e < 4; e++)
                    areg[j][e] = avalid[j] ? __ldg(x + abase[j] + ko[e]) : 0.0f;
                const float4 bv = *(const float4*)(wbase + (long)j * 32 * KTOT + k0);
                breg[j][0] = bv.x; breg[j][1] = bv.y; breg[j][2] = bv.z; breg[j][3] = bv.w;
            }
        }

        // ---- compute on buffer i&1 ----
        {
            const float* A  = smem + ((i & 1) ? OFF_A1 : OFF_A0) + wm * 64 * SLD;
            const float* Bs = smem + ((i & 1) ? OFF_B1 : OFF_B0) + wn * 32 * SLD;
            #pragma unroll
            for (int ks = 0; ks < 4; ks++) {
                const int cb = ks * 8 + lc * 2;
                float2 aLo[4], aHi[4], bF[4];
                #pragma unroll
                for (int tm = 0; tm < 4; tm++) {
                    aLo[tm] = *(const float2*)&A[(tm * 16 + lr) * SLD + cb];
                    aHi[tm] = *(const float2*)&A[(tm * 16 + lr + 8) * SLD + cb];
                }
                #pragma unroll
                for (int tn = 0; tn < 4; tn++)
                    bF[tn] = *(const float2*)&Bs[(tn * 8 + lr) * SLD + cb];
                #pragma unroll
                for (int tm = 0; tm < 4; tm++) {
                    uint32_t a0 = __float_as_uint(aLo[tm].x);
                    uint32_t a1 = __float_as_uint(aHi[tm].x);
                    uint32_t a2 = __float_as_uint(aLo[tm].y);
                    uint32_t a3 = __float_as_uint(aHi[tm].y);
                    #pragma unroll
                    for (int tn = 0; tn < 4; tn++)
                        mma_tf32(d[tm][tn], a0, a1, a2, a3,
                                 __float_as_uint(bF[tn].x), __float_as_uint(bF[tn].y));
                }
            }
        }

        // ---- stage chunk i+1 into the other buffer ----
        if (i + 1 < NCHUNK) {
            float* A  = smem + (((i + 1) & 1) ? OFF_A1 : OFF_A0);
            float* Bs = smem + (((i + 1) & 1) ? OFF_B1 : OFF_B0);
            #pragma unroll
            for (int j = 0; j < 4; j++) {
                int row = j * 32 + rsel;
                #pragma unroll
                for (int e = 0; e < 4; e++) {
                    A [row * SLD + colp + e * 2] = __uint_as_float(f2tf32(areg[j][e]));
                    Bs[row * SLD + colp + e * 2] = __uint_as_float(f2tf32(breg[j][e]));
                }
            }
        }
        __syncthreads();
    }

    // ---- epilogue: scatter to NCHW ----
    const int nbase = n0 + wn * 32;
    #pragma unroll
    for (int tm = 0; tm < 4; tm++) {
        #pragma unroll
        for (int h = 0; h < 2; h++) {
            const int m = m0 + wm * 64 + tm * 16 + h * 8 + lr;
            if (m >= M_TOT) continue;
            int b   = m / OHW2;
            int rem = m - b * OHW2;
            int oh  = rem / OHW;
            int ow  = rem - oh * OHW;
            const long obase = ((long)b * COUT + nbase) * OHW2 + oh * OHW + ow;
            #pragma unroll
            for (int tn = 0; tn < 4; tn++) {
                const int n_off = tn * 8 + lc * 2;
                out[obase + (long)n_off * OHW2]       = d[tm][tn][h * 2 + 0];
                out[obase + (long)(n_off + 1) * OHW2] = d[tm][tn][h * 2 + 1];
            }
        }
    }
}

extern "C" void kernel_launch(void* const* d_in, const int* in_sizes, int n_in,
                              void* d_out, int out_size) {
    const float* x = (const float*)d_in[0];
    const float* w = (const float*)d_in[1];
    float* out = (float*)d_out;

    cudaFuncSetAttribute(conv_mma_kernel,
                         cudaFuncAttributeMaxDynamicSharedMemorySize, SMEM_BYTES);

    dim3 grid((M_TOT + BM - 1) / BM, COUT / BN);   // (757, 2)
    conv_mma_kernel<<<grid, 256, SMEM_BYTES>>>(x, w, out);
}

// round 7
// speedup vs baseline: 2.8695x; 1.9757x over previous
#include <cuda_runtime.h>
#include <cstdint>

// Conv2d: x(32,128,112,112) fp32, w(256,128,3,3), stride 2, VALID -> out(32,256,55,55)
// Implicit GEMM, mma.sync m16n8k8 tf32. CTA tile 128x256, 3-stage cp.async pipeline.
// Pre-pass kernels round x/w to tf32 (rna) into __device__ scratch so the main
// loop is pure cp.async (no cvt, no register staging).

#define B_    32
#define CIN   128
#define HIN   112
#define WIN   112
#define COUT  256
#define OHW   55
#define OHW2  (OHW*OHW)          // 3025
#define KTOT  1152
#define M_TOT (B_*OHW2)          // 96800
#define CHW   (CIN*HIN*WIN)
#define XTOT  (B_*CHW)           // 51380224
#define WTOT  (COUT*KTOT)        // 294912

#define BM 128
#define BN 256
#define BK 32
#define NCHUNK (KTOT/BK)         // 36
#define NSTAGE 3
#define SLD 36                   // smem row stride in floats (pad 4)

#define ASTAGE (128*SLD)         // 4608 floats
#define BSTAGE (256*SLD)         // 9216 floats
#define OFF_B   (NSTAGE*ASTAGE)              // 13824
#define OFF_TAB (OFF_B + NSTAGE*BSTAGE)      // 41472
#define SMEM_FLOATS (OFF_TAB + KTOT)         // 42624
#define SMEM_BYTES  (SMEM_FLOATS*4)          // 170496

__device__ float g_xs[XTOT];
__device__ float g_ws[WTOT];

__device__ __forceinline__ float f2tf32f(float f) {
    uint32_t r;
    asm("cvt.rna.tf32.f32 %0, %1;" : "=r"(r) : "f"(f));
    return __uint_as_float(r);
}

__global__ void __launch_bounds__(256)
cvt_x_kernel(const float* __restrict__ x) {
    long i = ((long)blockIdx.x * 256 + threadIdx.x) * 4;
    if (i >= XTOT) return;
    float4 v = *(const float4*)(x + i);
    v.x = f2tf32f(v.x); v.y = f2tf32f(v.y); v.z = f2tf32f(v.z); v.w = f2tf32f(v.w);
    *(float4*)(g_xs + i) = v;
}

__global__ void __launch_bounds__(256)
cvt_w_kernel(const float* __restrict__ w) {
    long i = ((long)blockIdx.x * 256 + threadIdx.x) * 4;
    if (i >= WTOT) return;
    float4 v = *(const float4*)(w + i);
    v.x = f2tf32f(v.x); v.y = f2tf32f(v.y); v.z = f2tf32f(v.z); v.w = f2tf32f(v.w);
    *(float4*)(g_ws + i) = v;
}

__device__ __forceinline__ uint32_t smem_u32(const void* p) {
    uint32_t a;
    asm("{ .reg .u64 t; cvta.to.shared.u64 t, %1; cvt.u32.u64 %0, t; }" : "=r"(a) : "l"(p));
    return a;
}
__device__ __forceinline__ void cp4(uint32_t d, const float* s) {
    asm volatile("cp.async.ca.shared.global [%0], [%1], 4;"
                 :: "r"(d), "l"(__cvta_generic_to_global(s)) : "memory");
}
__device__ __forceinline__ void cp16(uint32_t d, const float* s) {
    asm volatile("cp.async.cg.shared.global [%0], [%1], 16;"
                 :: "r"(d), "l"(__cvta_generic_to_global(s)) : "memory");
}
__device__ __forceinline__ void cp_commit() {
    asm volatile("cp.async.commit_group;" ::: "memory");
}
__device__ __forceinline__ void cp_wait2() {
    asm volatile("cp.async.wait_group 2;" ::: "memory");
}

__device__ __forceinline__ void mma_tf32(float d[4],
                                         uint32_t a0, uint32_t a1, uint32_t a2, uint32_t a3,
                                         uint32_t b0, uint32_t b1) {
    asm volatile(
        "mma.sync.aligned.m16n8k8.row.col.f32.tf32.tf32.f32 "
        "{%0,%1,%2,%3}, {%4,%5,%6,%7}, {%8,%9}, {%0,%1,%2,%3};"
        : "+f"(d[0]), "+f"(d[1]), "+f"(d[2]), "+f"(d[3])
        : "r"(a0), "r"(a1), "r"(a2), "r"(a3), "r"(b0), "r"(b1));
}

__global__ void __launch_bounds__(256)
conv_mma_kernel(float* __restrict__ out) {
    extern __shared__ float smem[];
    int* offtab = (int*)(smem + OFF_TAB);

    const int tid  = threadIdx.x;
    const int wid  = tid >> 5;
    const int lane = tid & 31;
    const int m0   = blockIdx.x * BM;

    // producer mapping: kk = 4-k group (0..7), rsel = row selector (0..31)
    const int kk   = tid & 7;
    const int rsel = tid >> 3;

    // im2col offset table
    for (int k = tid; k < KTOT; k += 256) {
        int cin = k / 9, r = k - cin * 9;
        int kh = r / 3, kw = r - kh * 3;
        offtab[k] = cin * (HIN * WIN) + kh * WIN + kw;
    }

    // A row bases
    int abase[4];
    bool avalid[4];
    #pragma unroll
    for (int j = 0; j < 4; j++) {
        int m = m0 + j * 32 + rsel;
        avalid[j] = (m < M_TOT);
        int mm  = avalid[j] ? m : 0;
        int b   = mm / OHW2;
        int rem = mm - b * OHW2;
        int oh  = rem / OHW;
        int ow  = rem - oh * OHW;
        abase[j] = b * CHW + (2 * oh) * WIN + 2 * ow;
    }

    const uint32_t sb = smem_u32(smem);
    __syncthreads();   // offtab ready

    // ---- issue loads for one chunk into one stage ----
    auto issue = [&](int c, int s) {
        const int k0 = c * BK;
        int ko[4];
        #pragma unroll
        for (int e = 0; e < 4; e++) ko[e] = offtab[k0 + kk * 4 + e];
        const uint32_t Ab = sb + (s * ASTAGE) * 4;
        #pragma unroll
        for (int j = 0; j < 4; j++) {
            const int row = j * 32 + rsel;
            #pragma unroll
            for (int e = 0; e < 4; e++)
                cp4(Ab + (row * SLD + kk * 4 + e) * 4, g_xs + abase[j] + ko[e]);
        }
        const uint32_t Bb = sb + (OFF_B + s * BSTAGE) * 4;
        #pragma unroll
        for (int j = 0; j < 8; j++) {
            const int row = j * 32 + rsel;
            cp16(Bb + (row * SLD + kk * 4) * 4, g_ws + (long)row * KTOT + k0 + kk * 4);
        }
    };

    // ---- compute mapping: 8 warps = 2(M) x 4(N), warp tile 64x64 ----
    const int wm = wid & 1;
    const int wn = wid >> 1;
    const int lr = lane >> 2;      // 0..7
    const int lc = lane & 3;       // 0..3

    float d[4][8][4];
    #pragma unroll
    for (int a = 0; a < 4; a++)
        #pragma unroll
        for (int b = 0; b < 8; b++)
            #pragma unroll
            for (int c = 0; c < 4; c++) d[a][b][c] = 0.0f;

    // prologue: stages 0,1
    issue(0, 0); cp_commit();
    issue(1, 1); cp_commit();

    for (int i = 0; i < NCHUNK; i++) {
        const int c = i + 2;
        if (c < NCHUNK) issue(c, c % NSTAGE);
        cp_commit();
        cp_wait2();
        __syncthreads();

        const int st = i % NSTAGE;
        const float* A  = smem + st * ASTAGE + wm * 64 * SLD;
        const float* Bs = smem + OFF_B + st * BSTAGE + wn * 64 * SLD;

        #pragma unroll
        for (int ks = 0; ks < 4; ks++) {
            const int cb = ks * 8 + lc * 2;
            float2 aLo[4], aHi[4], bF[8];
            #pragma unroll
            for (int tm = 0; tm < 4; tm++) {
                aLo[tm] = *(const float2*)&A[(tm * 16 + lr) * SLD + cb];
                aHi[tm] = *(const float2*)&A[(tm * 16 + lr + 8) * SLD + cb];
            }
            #pragma unroll
            for (int tn = 0; tn < 8; tn++)
                bF[tn] = *(const float2*)&Bs[(tn * 8 + lr) * SLD + cb];
            #pragma unroll
            for (int tm = 0; tm < 4; tm++) {
                const uint32_t a0 = __float_as_uint(aLo[tm].x);
                const uint32_t a1 = __float_as_uint(aHi[tm].x);
                const uint32_t a2 = __float_as_uint(aLo[tm].y);
                const uint32_t a3 = __float_as_uint(aHi[tm].y);
                #pragma unroll
                for (int tn = 0; tn < 8; tn++)
                    mma_tf32(d[tm][tn], a0, a1, a2, a3,
                             __float_as_uint(bF[tn].x), __float_as_uint(bF[tn].y));
            }
        }
        __syncthreads();
    }

    // ---- epilogue: scatter to NCHW ----
    const int nbase = wn * 64;
    #pragma unroll
    for (int tm = 0; tm < 4; tm++) {
        #pragma unroll
        for (int h = 0; h < 2; h++) {
            const int m = m0 + wm * 64 + tm * 16 + h * 8 + lr;
            if (m >= M_TOT) continue;
            int b   = m / OHW2;
            int rem = m - b * OHW2;
            int oh  = rem / OHW;
            int ow  = rem - oh * OHW;
            const long obase = ((long)b * COUT + nbase) * OHW2 + oh * OHW + ow;
            #pragma unroll
            for (int tn = 0; tn < 8; tn++) {
                const int n_off = tn * 8 + lc * 2;
                out[obase + (long)n_off * OHW2]       = d[tm][tn][h * 2 + 0];
                out[obase + (long)(n_off + 1) * OHW2] = d[tm][tn][h * 2 + 1];
            }
        }
    }
}

extern "C" void kernel_launch(void* const* d_in, const int* in_sizes, int n_in,
                              void* d_out, int out_size) {
    const float* x = (const float*)d_in[0];
    const float* w = (const float*)d_in[1];
    float* out = (float*)d_out;

    cvt_x_kernel<<<(XTOT / 4 + 255) / 256, 256>>>(x);
    cvt_w_kernel<<<(WTOT / 4 + 255) / 256, 256>>>(w);

    cudaFuncSetAttribute(conv_mma_kernel,
                         cudaFuncAttributeMaxDynamicSharedMemorySize, SMEM_BYTES);

    dim3 grid((M_TOT + BM - 1) / BM, 1);   // 757
    conv_mma_kernel<<<grid, 256, SMEM_BYTES>>>(out);
}